// round 1
// baseline (speedup 1.0000x reference)
#include <cuda_runtime.h>

#define DD   48
#define HW   2304            // 48*48
#define DHW  110592          // 48^3
#define CIN  128
#define COUT 128
#define NK   512
#define KK   3456            // 128*27
#define LOG2E 1.4426950408889634f

// ---------------- scratch (device globals; no allocation allowed) ----------------
__device__ float d_y[COUT * DHW];     // conv+relu output, 56.6 MB
__device__ float d_wt[COUT * KK];     // transposed weights [cin][tap][cout]
__device__ float d_mean[COUT];
__device__ float d_rstd[COUT];
__device__ float d_fk2[NK * 128];     // 2*log2e * normalized keypoint features, [n][c]
__device__ float d_nn[NK];            // log2e * ||fk_n||^2

__device__ __forceinline__ float exp2a(float x) {
    float r;
    asm("ex2.approx.ftz.f32 %0, %1;" : "=f"(r) : "f"(x));
    return r;
}

// ---------------- kernel 0: transpose W0 (co,cin,tap) -> (cin,tap,co) ----------------
__global__ void transpose_w_kernel(const float* __restrict__ W0) {
    int i = blockIdx.x * 256 + threadIdx.x;          // 442368 = 1728*256 exactly
    int co  = i & 127;
    int tap = (i >> 7) % 27;
    int cin = i / KK;
    d_wt[i] = W0[co * KK + cin * 27 + tap];
}

// ---------------- kernel 1: conv3d(3x3x3, pad1) + bias + relu ----------------
// block: 256 thr, computes a 4x4x4 spatial tile x all 128 couts.
// thread mapping: gidx = tid&15 -> (sz,sy); sx = 0..3 per-thread; co_base = (tid>>4)*8
__global__ void __launch_bounds__(256) conv_relu_kernel(const float* __restrict__ feats,
                                                        const float* __restrict__ b0) {
    __shared__ __align__(16) float patch[216];       // 6x6x6
    __shared__ __align__(16) float wsm[KK];          // [tap][co] for current cin

    const int tid = threadIdx.x;
    const int blk = blockIdx.x;
    const int tz = blk / 144, ty = (blk / 12) % 12, tx = blk % 12;

    const int gidx = tid & 15;
    const int sz = gidx >> 2, sy = gidx & 3;
    const int co_base = (tid >> 4) * 8;

    float acc[4][8];
#pragma unroll
    for (int i = 0; i < 4; i++)
#pragma unroll
        for (int j = 0; j < 8; j++) acc[i][j] = 0.f;

    // precompute patch-load coords for this thread (tid<216 loads one element)
    int gz = 0, gy = 0, gx = 0;
    bool inb = false;
    if (tid < 216) {
        int pz = tid / 36, py = (tid / 6) % 6, px = tid % 6;
        gz = tz * 4 + pz - 1;
        gy = ty * 4 + py - 1;
        gx = tx * 4 + px - 1;
        inb = (gz >= 0 && gz < DD && gy >= 0 && gy < DD && gx >= 0 && gx < DD);
    }

    for (int cin = 0; cin < CIN; ++cin) {
        if (tid < 216) {
            float v = 0.f;
            if (inb) {
                if (cin < 125)      v = feats[cin * DHW + gz * HW + gy * 48 + gx];
                else if (cin == 125) v = (2.0f / 47.0f) * (float)gx - 1.0f;
                else if (cin == 126) v = (2.0f / 47.0f) * (float)gy - 1.0f;
                else                 v = (2.0f / 47.0f) * (float)gz - 1.0f;
            }
            patch[tid] = v;
        }
        const float* wsrc = &d_wt[cin * KK];
        for (int i = tid; i < KK; i += 256) wsm[i] = wsrc[i];
        __syncthreads();

#pragma unroll
        for (int kz = 0; kz < 3; ++kz)
#pragma unroll
        for (int ky = 0; ky < 3; ++ky)
#pragma unroll
        for (int kx = 0; kx < 3; ++kx) {
            const int base = (sz + kz) * 36 + (sy + ky) * 6 + kx;
            float in[4];
            in[0] = patch[base + 0];
            in[1] = patch[base + 1];
            in[2] = patch[base + 2];
            in[3] = patch[base + 3];
            const int tap = (kz * 3 + ky) * 3 + kx;
            float4 wa = *reinterpret_cast<const float4*>(&wsm[tap * 128 + co_base]);
            float4 wb = *reinterpret_cast<const float4*>(&wsm[tap * 128 + co_base + 4]);
            float w[8] = {wa.x, wa.y, wa.z, wa.w, wb.x, wb.y, wb.z, wb.w};
#pragma unroll
            for (int i = 0; i < 4; i++)
#pragma unroll
                for (int j = 0; j < 8; j++)
                    acc[i][j] = fmaf(in[i], w[j], acc[i][j]);
        }
        __syncthreads();
    }

    // write bias + relu
    const int z = tz * 4 + sz, y = ty * 4 + sy, xb = tx * 4;
#pragma unroll
    for (int j = 0; j < 8; j++) {
        const int co = co_base + j;
        const float b = b0[co];
        float* dst = &d_y[co * DHW + z * HW + y * 48 + xb];
#pragma unroll
        for (int i = 0; i < 4; i++) {
            dst[i] = fmaxf(acc[i][j] + b, 0.f);
        }
    }
}

// ---------------- kernel 2: per-channel mean / rstd (InstanceNorm stats) ----------------
__global__ void __launch_bounds__(256) stats_kernel() {
    const int c = blockIdx.x;
    const int tid = threadIdx.x;
    const float* src = &d_y[c * DHW];
    float s = 0.f, s2 = 0.f;
    for (int i = tid; i < DHW; i += 256) {
        float v = src[i];
        s += v;
        s2 += v * v;
    }
    __shared__ float rs[256], rs2[256];
    rs[tid] = s; rs2[tid] = s2;
    __syncthreads();
    for (int o = 128; o > 0; o >>= 1) {
        if (tid < o) { rs[tid] += rs[tid + o]; rs2[tid] += rs2[tid + o]; }
        __syncthreads();
    }
    if (tid == 0) {
        float mean = rs[0] * (1.0f / (float)DHW);
        float var  = rs2[0] * (1.0f / (float)DHW) - mean * mean;
        d_mean[c] = mean;
        d_rstd[c] = rsqrtf(var + 1e-5f);
    }
}

// ---------------- kernel 3: trilinear sample at keypoints, normalize, scale ----------------
__global__ void __launch_bounds__(128) sample_kernel(const float* __restrict__ kpts) {
    const int n = blockIdx.x;
    const int c = threadIdx.x;
    __shared__ float pt[3];
    if (c < 3) pt[c] = kpts[n * 3 + c];
    __syncthreads();

    const float ix = (pt[0] + 1.0f) * 0.5f * 47.0f;
    const float iy = (pt[1] + 1.0f) * 0.5f * 47.0f;
    const float iz = (pt[2] + 1.0f) * 0.5f * 47.0f;
    const float x0f = floorf(ix), y0f = floorf(iy), z0f = floorf(iz);
    const float wx = ix - x0f, wy = iy - y0f, wz = iz - z0f;
    int x0 = min(max((int)x0f, 0), 47);
    int y0 = min(max((int)y0f, 0), 47);
    int z0 = min(max((int)z0f, 0), 47);
    int x1 = min(x0 + 1, 47), y1 = min(y0 + 1, 47), z1 = min(z0 + 1, 47);

    const float* vol = &d_y[c * DHW];
    float c000 = vol[z0 * HW + y0 * 48 + x0];
    float c001 = vol[z0 * HW + y0 * 48 + x1];
    float c010 = vol[z0 * HW + y1 * 48 + x0];
    float c011 = vol[z0 * HW + y1 * 48 + x1];
    float c100 = vol[z1 * HW + y0 * 48 + x0];
    float c101 = vol[z1 * HW + y0 * 48 + x1];
    float c110 = vol[z1 * HW + y1 * 48 + x0];
    float c111 = vol[z1 * HW + y1 * 48 + x1];

    float v = c000 * ((1 - wz) * (1 - wy) * (1 - wx))
            + c001 * ((1 - wz) * (1 - wy) * wx)
            + c010 * ((1 - wz) * wy * (1 - wx))
            + c011 * ((1 - wz) * wy * wx)
            + c100 * (wz * (1 - wy) * (1 - wx))
            + c101 * (wz * (1 - wy) * wx)
            + c110 * (wz * wy * (1 - wx))
            + c111 * (wz * wy * wx);

    // normalization is per-channel affine, so it commutes with trilinear interp
    float f = (v - d_mean[c]) * d_rstd[c];
    d_fk2[n * 128 + c] = 2.0f * LOG2E * f;

    __shared__ float red[128];
    red[c] = f * f;
    __syncthreads();
    for (int o = 64; o > 0; o >>= 1) {
        if (c < o) red[c] += red[c + o];
        __syncthreads();
    }
    if (c == 0) d_nn[n] = LOG2E * red[0];
}

// ---------------- kernel 4: distances + softmax + weighted displacement ----------------
// weight_n(g) proportional to exp(2*dot(fg_g,fk_n) - ||fk_n||^2)  (||fg_g||^2 cancels)
// computed in log2 domain with online max-rescale.
// block: 256 thr = 32 voxels (lane=g) x 8 keypoint groups (q). 16 chunks of 32 kpts.
__global__ void __launch_bounds__(256) softmax_disp_kernel(const float* __restrict__ disp,
                                                           float* __restrict__ out) {
    __shared__ __align__(16) float fgs[128 * 32];   // [c][g]
    __shared__ __align__(16) float fks[32 * 128];   // [n_local][c]  (reused as reduction buf)
    __shared__ float nns[32];
    __shared__ float dsm[NK * 3];

    const int tid = threadIdx.x;
    const int g0 = blockIdx.x * 32;
    const int g = tid & 31;
    const int q = tid >> 5;

    for (int i = tid; i < 4096; i += 256) {
        int c = i >> 5, gg = i & 31;
        fgs[i] = (d_y[c * DHW + g0 + gg] - d_mean[c]) * d_rstd[c];
    }
    for (int i = tid; i < NK * 3; i += 256) dsm[i] = disp[i];

    float m = -1e30f, S = 0.f, Wx = 0.f, Wy = 0.f, Wz = 0.f;

    for (int ch = 0; ch < 16; ++ch) {
        __syncthreads();
        const float* fsrc = &d_fk2[ch * 4096];
        for (int i = tid; i < 4096; i += 256) fks[i] = fsrc[i];
        if (tid < 32) nns[tid] = d_nn[ch * 32 + tid];
        __syncthreads();

        const int nl0 = q * 4;
        float a0 = -nns[nl0 + 0];
        float a1 = -nns[nl0 + 1];
        float a2 = -nns[nl0 + 2];
        float a3 = -nns[nl0 + 3];

        const float* k0p = &fks[(nl0 + 0) * 128];
        const float* k1p = &fks[(nl0 + 1) * 128];
        const float* k2p = &fks[(nl0 + 2) * 128];
        const float* k3p = &fks[(nl0 + 3) * 128];

#pragma unroll 8
        for (int c = 0; c < 128; c += 4) {
            float f0 = fgs[(c + 0) * 32 + g];
            float f1 = fgs[(c + 1) * 32 + g];
            float f2 = fgs[(c + 2) * 32 + g];
            float f3 = fgs[(c + 3) * 32 + g];
            float4 k0 = *reinterpret_cast<const float4*>(k0p + c);
            float4 k1 = *reinterpret_cast<const float4*>(k1p + c);
            float4 k2 = *reinterpret_cast<const float4*>(k2p + c);
            float4 k3 = *reinterpret_cast<const float4*>(k3p + c);
            a0 = fmaf(f0, k0.x, a0); a0 = fmaf(f1, k0.y, a0); a0 = fmaf(f2, k0.z, a0); a0 = fmaf(f3, k0.w, a0);
            a1 = fmaf(f0, k1.x, a1); a1 = fmaf(f1, k1.y, a1); a1 = fmaf(f2, k1.z, a1); a1 = fmaf(f3, k1.w, a1);
            a2 = fmaf(f0, k2.x, a2); a2 = fmaf(f1, k2.y, a2); a2 = fmaf(f2, k2.z, a2); a2 = fmaf(f3, k2.w, a2);
            a3 = fmaf(f0, k3.x, a3); a3 = fmaf(f1, k3.y, a3); a3 = fmaf(f2, k3.z, a3); a3 = fmaf(f3, k3.w, a3);
        }

        float m8 = fmaxf(fmaxf(a0, a1), fmaxf(a2, a3));
        if (m8 > m) {
            float cs = exp2a(m - m8);
            S *= cs; Wx *= cs; Wy *= cs; Wz *= cs;
            m = m8;
        }
        const int nb = (ch * 32 + nl0) * 3;
        float e0 = exp2a(a0 - m);
        float e1 = exp2a(a1 - m);
        float e2 = exp2a(a2 - m);
        float e3 = exp2a(a3 - m);
        S += e0 + e1 + e2 + e3;
        Wx = fmaf(e0, dsm[nb + 0], fmaf(e1, dsm[nb + 3], fmaf(e2, dsm[nb + 6], fmaf(e3, dsm[nb + 9],  Wx))));
        Wy = fmaf(e0, dsm[nb + 1], fmaf(e1, dsm[nb + 4], fmaf(e2, dsm[nb + 7], fmaf(e3, dsm[nb + 10], Wy))));
        Wz = fmaf(e0, dsm[nb + 2], fmaf(e1, dsm[nb + 5], fmaf(e2, dsm[nb + 8], fmaf(e3, dsm[nb + 11], Wz))));
    }

    // combine across the 8 q-groups per voxel (reuse fks as reduction buffer)
    __syncthreads();
    float* red = fks;
    red[0 * 256 + tid] = m;
    red[1 * 256 + tid] = S;
    red[2 * 256 + tid] = Wx;
    red[3 * 256 + tid] = Wy;
    red[4 * 256 + tid] = Wz;
    __syncthreads();
    if (tid < 32) {
        float mm = -1e30f;
#pragma unroll
        for (int qq = 0; qq < 8; qq++) mm = fmaxf(mm, red[qq * 32 + tid]);
        float Ss = 0.f, Sx = 0.f, Sy = 0.f, Sz = 0.f;
#pragma unroll
        for (int qq = 0; qq < 8; qq++) {
            float cs = exp2a(red[qq * 32 + tid] - mm);
            Ss = fmaf(red[256 + qq * 32 + tid], cs, Ss);
            Sx = fmaf(red[512 + qq * 32 + tid], cs, Sx);
            Sy = fmaf(red[768 + qq * 32 + tid], cs, Sy);
            Sz = fmaf(red[1024 + qq * 32 + tid], cs, Sz);
        }
        float inv = 1.0f / Ss;
        out[0 * DHW + g0 + tid] = Sx * inv;
        out[1 * DHW + g0 + tid] = Sy * inv;
        out[2 * DHW + g0 + tid] = Sz * inv;
    }
}

// ---------------- launch ----------------
extern "C" void kernel_launch(void* const* d_in, const int* in_sizes, int n_in,
                              void* d_out, int out_size) {
    const float* kpts  = (const float*)d_in[0];  // (1,512,3)
    const float* disp  = (const float*)d_in[1];  // (1,512,3)
    const float* feats = (const float*)d_in[2];  // (1,125,48,48,48)
    const float* W0    = (const float*)d_in[3];  // (128,128,3,3,3)
    const float* b0    = (const float*)d_in[4];  // (128,)
    float* out = (float*)d_out;                  // (1,3,48,48,48)

    transpose_w_kernel<<<1728, 256>>>(W0);
    conv_relu_kernel<<<1728, 256>>>(feats, b0);
    stats_kernel<<<128, 256>>>();
    sample_kernel<<<NK, 128>>>(kpts);
    softmax_disp_kernel<<<DHW / 32, 256>>>(disp, out);
}